// round 1
// baseline (speedup 1.0000x reference)
#include <cuda_runtime.h>
#include <cstdint>

#define BB 128
#define TT 4096
#define NP (BB*TT)          // 524288 positions
#define CLIPV 100000.0f
#define K10  (-14.4269504088896340f)   // -10*log2(e)
#define KT2  (-2.8853900817779268f)    // -2*log2(e)  (tanh)
#define KS1  (-1.4426950408889634f)    // -1*log2(e)  (sigmoid)
#define LFR  (0.14426950408889634f)    // 0.1*log2(e)

// ---------------- scratch (device-global, no allocation) ----------------
__device__ float4 g_pA[(TT+4)*BB];   // psnow, prain, g(melt gate), m2(melt cap)
__device__ float4 g_pB[(TT+4)*BB];   // smax, pet+qmax, pet/smax, f*0.1*log2e
__device__ float  g_qm[(TT+4)*BB];   // qmax
__device__ float  g_s1s[TT*BB];      // s1 trajectory

// ---------------- helpers ----------------
typedef unsigned long long ull;

__device__ __forceinline__ float ex2f(float x){ float y; asm("ex2.approx.f32 %0, %1;" : "=f"(y) : "f"(x)); return y; }
__device__ __forceinline__ float rcpf(float x){ float y; asm("rcp.approx.f32 %0, %1;" : "=f"(y) : "f"(x)); return y; }
// heaviside(x) == (tanh(5x)+1)/2 == sigma(10x), exact identity
__device__ __forceinline__ float hv10(float x){ return rcpf(1.f + ex2f(K10 * x)); }
__device__ __forceinline__ float tanh_fast(float x){ return fmaf(2.f, rcpf(1.f + ex2f(KT2 * x)), -1.f); }
__device__ __forceinline__ float sigm(float x){ return rcpf(1.f + ex2f(KS1 * x)); }

__device__ __forceinline__ ull pk(float lo, float hi){ ull r; asm("mov.b64 %0, {%1, %2};" : "=l"(r) : "f"(lo), "f"(hi)); return r; }
__device__ __forceinline__ void upk(ull v, float& lo, float& hi){ asm("mov.b64 {%0, %1}, %2;" : "=f"(lo), "=f"(hi) : "l"(v)); }
__device__ __forceinline__ ull ffma2(ull a, ull b, ull c){ ull d; asm("fma.rn.f32x2 %0, %1, %2, %3;" : "=l"(d) : "l"(a), "l"(b), "l"(c)); return d; }
__device__ __forceinline__ ull fadd2(ull a, ull b){ ull d; asm("add.rn.f32x2 %0, %1, %2;" : "=l"(d) : "l"(a), "l"(b)); return d; }

// ---------------- shared-memory layout for the MLP kernel ----------------
// all weights duplicated (w,w) so LDS.128 yields two f32x2 operands directly
#define W1D_OFF 0                 // 256*32 floats (16 ull per hidden unit, k padded to 16)
#define W2D_OFF (W1D_OFF + 256*32) // 256*128 floats
#define W3D_OFF (W2D_OFF + 256*128)// 6*128 floats
#define B1D_OFF (W3D_OFF + 6*128)  // 512 floats (dup)
#define B2_OFF  (B1D_OFF + 512)    // 64
#define B3_OFF  (B2_OFF + 64)      // 8
#define SMEM_FLOATS (B3_OFF + 8)
#define SMEM_BYTES (SMEM_FLOATS * 4)

__device__ __forceinline__ void emit_consts(int idx, float pet, float tmean, float prcp, const float p[6]){
    float tmin = p[0], tmax = p[1], ddf = p[2], f = p[3], sm0 = p[4], qm0 = p[5];
    float tmn   = tmin * (-3.f);
    float sn    = hv10(tmn - tmean);
    float psnow = sn * prcp;
    float prain = prcp - psnow;          // == heaviside(t-tmn)*p (tanh odd)
    float tmx3  = tmax * 3.f;
    float g     = hv10(tmean - tmx3);
    float m2    = (ddf * 5.f) * (tmean - tmx3);
    float smax  = fmaf(sm0, 1400.f, 100.f);
    float qmax  = fmaf(qm0, 40.f, 10.f);
    float fr2   = f * LFR;               // (f/10)*log2e
    float Bc    = pet * rcpf(smax);
    g_pA[idx] = make_float4(psnow, prain, g, m2);
    g_pB[idx] = make_float4(smax, pet + qmax, Bc, fr2);
    g_qm[idx] = qmax;
}

// ============ kernel 1: fused MLP + per-step constant precompute ============
__global__ __launch_bounds__(256, 1)
void mlp_kernel(const float* __restrict__ in,
                const float* __restrict__ w1, const float* __restrict__ b1,
                const float* __restrict__ w2, const float* __restrict__ b2,
                const float* __restrict__ w3, const float* __restrict__ b3)
{
    extern __shared__ float sm[];
    float* w1d = sm + W1D_OFF;
    float* w2d = sm + W2D_OFF;
    float* w3d = sm + W3D_OFF;
    float* b1d = sm + B1D_OFF;
    float* b2s = sm + B2_OFF;
    float* b3s = sm + B3_OFF;

    // stage duplicated weights
    for (int idx = threadIdx.x; idx < 15*256; idx += 256){
        int k = idx / 256, i = idx % 256;
        float w = w1[idx];
        w1d[i*32 + 2*k] = w; w1d[i*32 + 2*k + 1] = w;
    }
    for (int i = threadIdx.x; i < 256; i += 256){
        w1d[i*32 + 30] = 0.f; w1d[i*32 + 31] = 0.f;   // k=15 pad
        float bb = b1[i];
        b1d[2*i] = bb; b1d[2*i+1] = bb;
    }
    for (int idx = threadIdx.x; idx < 256*64; idx += 256){
        float w = w2[idx];
        w2d[2*idx] = w; w2d[2*idx+1] = w;             // [i*128 + 2j]
    }
    for (int idx = threadIdx.x; idx < 64*6; idx += 256){
        int j = idx / 6, m = idx % 6;
        float w = w3[idx];
        w3d[m*128 + 2*j] = w; w3d[m*128 + 2*j + 1] = w;
    }
    if (threadIdx.x < 64) b2s[threadIdx.x] = b2[threadIdx.x];
    if (threadIdx.x < 8)  b3s[threadIdx.x] = (threadIdx.x < 6) ? b3[threadIdx.x] : 0.f;
    __syncthreads();

    int pair = blockIdx.x * 256 + threadIdx.x;   // 0..262143
    int idx0 = pair * 2;                          // [t][b] enumeration, b fast
    int t  = idx0 >> 7;
    int b0 = idx0 & 127;                          // even; b0+1 < 128

    // load inputs for both lanes (80B aligned chunks)
    float v0[20], v1[20];
    {
        const float4* q0 = (const float4*)(in + ((size_t)b0       * TT + t) * 20);
        const float4* q1 = (const float4*)(in + ((size_t)(b0 + 1) * TT + t) * 20);
        #pragma unroll
        for (int r = 0; r < 5; r++){
            float4 a = q0[r]; v0[4*r]=a.x; v0[4*r+1]=a.y; v0[4*r+2]=a.z; v0[4*r+3]=a.w;
            float4 c = q1[r]; v1[4*r]=c.x; v1[4*r+1]=c.y; v1[4*r+2]=c.z; v1[4*r+3]=c.w;
        }
    }
    ull attr2[16];
    #pragma unroll
    for (int k = 0; k < 15; k++) attr2[k] = pk(v0[5+k], v1[5+k]);
    attr2[15] = 0ULL;

    ull acc[64];
    #pragma unroll
    for (int j = 0; j < 64; j++){ float bb = b2s[j]; acc[j] = pk(bb, bb); }

    // layer 1 (15->256, tanh) streamed into layer 2 accumulators (256->64)
    #pragma unroll 1
    for (int i = 0; i < 256; i++){
        const ulonglong2* wq = (const ulonglong2*)(w1d + i*32);
        ull s = *((const ull*)b1d + i);
        #pragma unroll
        for (int kk = 0; kk < 8; kk++){
            ulonglong2 wv = wq[kk];
            s = ffma2(attr2[2*kk],   wv.x, s);
            s = ffma2(attr2[2*kk+1], wv.y, s);
        }
        float lo, hi; upk(s, lo, hi);
        ull tt = pk(tanh_fast(lo), tanh_fast(hi));
        const ulonglong2* w2q = (const ulonglong2*)(w2d + i*128);
        #pragma unroll
        for (int jj = 0; jj < 32; jj++){
            ulonglong2 wv = w2q[jj];
            acc[2*jj]   = ffma2(tt, wv.x, acc[2*jj]);
            acc[2*jj+1] = ffma2(tt, wv.y, acc[2*jj+1]);
        }
    }
    // tanh layer 2 output in place
    #pragma unroll
    for (int j = 0; j < 64; j++){
        float lo, hi; upk(acc[j], lo, hi);
        acc[j] = pk(tanh_fast(lo), tanh_fast(hi));
    }
    // layer 3 (64->6) + sigmoid
    float p0[6], p1[6];
    #pragma unroll
    for (int m = 0; m < 6; m++){
        const ulonglong2* w3q = (const ulonglong2*)(w3d + m*128);
        float bb = b3s[m];
        ull sA = pk(bb, bb), sB = 0ULL;
        #pragma unroll
        for (int jj = 0; jj < 32; jj++){
            ulonglong2 wv = w3q[jj];
            sA = ffma2(acc[2*jj],   wv.x, sA);
            sB = ffma2(acc[2*jj+1], wv.y, sB);
        }
        ull sT = fadd2(sA, sB);
        float lo, hi; upk(sT, lo, hi);
        p0[m] = sigm(lo); p1[m] = sigm(hi);
    }
    emit_consts(idx0,     v0[0], v0[1], v0[2], p0);
    emit_consts(idx0 + 1, v1[0], v1[1], v1[2], p1);
}

// ============ kernel 2: the serial scan (128 independent chains) ============
__global__ void scan_kernel()
{
    const int b = blockIdx.x * 32 + threadIdx.x;     // 4 CTAs x 32
    const float4* pA = g_pA + b;
    const float4* pB = g_pB + b;
    const float*  pQ = g_qm + b;

    float4 bA[4], bBv[4]; float bQ[4];
    #pragma unroll
    for (int k = 0; k < 4; k++){ bA[k] = pA[k*BB]; bBv[k] = pB[k*BB]; bQ[k] = pQ[k*BB]; }

    float s0 = 0.f, s1 = 0.f;
    #pragma unroll 1
    for (int t = 0; t < TT; t += 4){
        #pragma unroll
        for (int u = 0; u < 4; u++){
            float4 a = bA[u]; float4 c = bBv[u]; float qm = bQ[u];
            int tn = t + 4 + u;                       // prefetch ~4 steps ahead
            bA[u] = pA[tn*BB]; bBv[u] = pB[tn*BB]; bQ[u] = pQ[tn*BB];

            // snow bucket
            float hs0  = rcpf(1.f + ex2f(K10 * s0));
            float melt = a.z * hs0 * fminf(s0, a.w);
            float ds0  = fminf(fmaxf(a.x - melt, -CLIPV), CLIPV);
            s0 += ds0;

            // soil bucket: loss = et + qsub + qsurf
            //  = h1*[above*(pet+qmax+d) + below*(pet/smax*s1 + qmax*exp(fr*d))], d = s1-smax
            float d     = s1 - c.x;
            float above = rcpf(1.f + ex2f(K10 * d));   // saturates safely (inf->0)
            float below = 1.f - above;
            float h1    = rcpf(1.f + ex2f(K10 * s1));
            float E     = ex2f(c.w * d);
            float v     = fmaf(qm, E, c.z * s1);
            float w     = fmaf(below, v, above * (c.y + d));
            float loss  = h1 * w;
            float ds1   = fminf(fmaxf(a.y + melt - loss, -CLIPV), CLIPV);
            s1 += ds1;

            g_s1s[(t + u) * BB + b] = s1;
        }
    }
}

// ============ kernel 3: q = qsub+qsurf from stored s1 (fully parallel) ============
__global__ __launch_bounds__(256)
void qout_kernel(float* __restrict__ out)
{
    int idx = blockIdx.x * 256 + threadIdx.x;
    if (idx >= NP) return;
    float  s1 = g_s1s[idx];
    float4 c  = g_pB[idx];
    float  qm = g_qm[idx];
    float d     = s1 - c.x;
    float above = rcpf(1.f + ex2f(K10 * d));
    float below = 1.f - above;
    float h1    = rcpf(1.f + ex2f(K10 * s1));
    float E     = ex2f(c.w * d);
    float qq    = h1 * (above * (qm + d) + below * qm * E);
    int t = idx >> 7, b = idx & 127;
    out[(size_t)b * TT + t] = qq;
}

// ---------------- launch ----------------
extern "C" void kernel_launch(void* const* d_in, const int* in_sizes, int n_in,
                              void* d_out, int out_size)
{
    const float* in = (const float*)d_in[0];
    const float* w1 = (const float*)d_in[1];
    const float* b1 = (const float*)d_in[2];
    const float* w2 = (const float*)d_in[3];
    const float* b2 = (const float*)d_in[4];
    const float* w3 = (const float*)d_in[5];
    const float* b3 = (const float*)d_in[6];
    float* out = (float*)d_out;

    cudaFuncSetAttribute(mlp_kernel, cudaFuncAttributeMaxDynamicSharedMemorySize, SMEM_BYTES);
    mlp_kernel<<<NP/512, 256, SMEM_BYTES>>>(in, w1, b1, w2, b2, w3, b3);
    scan_kernel<<<4, 32>>>();
    qout_kernel<<<(NP + 255)/256, 256>>>(out);
}

// round 2
// speedup vs baseline: 1.3180x; 1.3180x over previous
#include <cuda_runtime.h>
#include <cstdint>

#define BB 128
#define TT 4096
#define NP (BB*TT)
#define CLIPV 100000.0f
#define K10  (-14.4269504088896340f)   // -10*log2(e)
#define NK10 ( 14.4269504088896340f)   // +10*log2(e)
#define KT2  (-2.8853900817779268f)    // -2*log2(e)  (tanh)
#define KS1  (-1.4426950408889634f)    // -1*log2(e)  (sigmoid)
#define LFR  (0.14426950408889634f)    // 0.1*log2(e)

// ---------------- scratch (device-global, no allocation) ----------------
__device__ float4 g_pA[(TT+16)*BB];   // psnow, prain, g(melt gate), m2(melt cap)
__device__ float4 g_pB[(TT+16)*BB];   // C1=-K10*smax, C3=pet+qmax-smax, Bc=pet/smax, fr2
__device__ float2 g_pC[(TT+16)*BB];   // C2=log2(qmax)-fr2*smax, C4=qmax-smax
__device__ float  g_s1s[TT*BB];       // s1 trajectory

typedef unsigned long long ull;

__device__ __forceinline__ float ex2f(float x){ float y; asm("ex2.approx.f32 %0, %1;" : "=f"(y) : "f"(x)); return y; }
__device__ __forceinline__ float rcpf(float x){ float y; asm("rcp.approx.f32 %0, %1;" : "=f"(y) : "f"(x)); return y; }
__device__ __forceinline__ float lg2f(float x){ float y; asm("lg2.approx.f32 %0, %1;" : "=f"(y) : "f"(x)); return y; }
// heaviside(x) == (tanh(5x)+1)/2 == sigma(10x), exact identity
__device__ __forceinline__ float hv10(float x){ return rcpf(1.f + ex2f(K10 * x)); }
__device__ __forceinline__ float tanh_fast(float x){ return fmaf(2.f, rcpf(1.f + ex2f(KT2 * x)), -1.f); }
__device__ __forceinline__ float sigm(float x){ return rcpf(1.f + ex2f(KS1 * x)); }
__device__ __forceinline__ float clipf(float x){ return fminf(fmaxf(x, -CLIPV), CLIPV); }

__device__ __forceinline__ ull pk(float lo, float hi){ ull r; asm("mov.b64 %0, {%1, %2};" : "=l"(r) : "f"(lo), "f"(hi)); return r; }
__device__ __forceinline__ void upk(ull v, float& lo, float& hi){ asm("mov.b64 {%0, %1}, %2;" : "=f"(lo), "=f"(hi) : "l"(v)); }
__device__ __forceinline__ ull ffma2(ull a, ull b, ull c){ ull d; asm("fma.rn.f32x2 %0, %1, %2, %3;" : "=l"(d) : "l"(a), "l"(b), "l"(c)); return d; }
__device__ __forceinline__ ull tanh2(ull v){ float lo, hi; upk(v, lo, hi); return pk(tanh_fast(lo), tanh_fast(hi)); }

// ---------------- SMEM layout for mlp kernel (floats) ----------------
#define ATT_OFF 0                       // attrs_s[15][128]
#define PT_OFF  (ATT_OFF + 15*128)      // pt_s[3][128]
#define W1_OFF  (PT_OFF + 3*128)        // w1_s[15][256]
#define B1_OFF  (W1_OFF + 15*256)       // 256
#define W2_OFF  (B1_OFF + 256)          // w2_s[256][64]
#define B2_OFF  (W2_OFF + 256*64)       // 64
#define W3_OFF  (B2_OFF + 64)           // w3_s[6][64]
#define B3_OFF  (W3_OFF + 6*64)         // 8
#define H_OFF   (B3_OFF + 8)            // h_s[256][128] (reused as g_s[64][128])
#define SMEM_FLOATS (H_OFF + 256*128)
#define SMEM_BYTES (SMEM_FLOATS * 4)    // 224032 B

__device__ __forceinline__ void emit_consts(int idx, float pet, float tmean, float prcp, const float p[6]){
    float tmin = p[0], tmax = p[1], ddf = p[2], f = p[3], sm0 = p[4], qm0 = p[5];
    float smax = fmaf(sm0, 1400.f, 100.f);
    float qmax = fmaf(qm0, 40.f, 10.f);
    float tmn   = tmin * (-3.f);
    float psnow = hv10(tmn - tmean) * prcp;
    float prain = prcp - psnow;
    float tmx3  = tmax * 3.f;
    float g     = hv10(tmean - tmx3);
    float m2    = (ddf * 5.f) * (tmean - tmx3);
    float fr2   = f * LFR;
    float C1    = NK10 * smax;
    float C3    = pet + qmax - smax;
    float Bc    = pet * rcpf(smax);
    float C2    = lg2f(qmax) - fr2 * smax;
    float C4    = qmax - smax;
    g_pA[idx] = make_float4(psnow, prain, g, m2);
    g_pB[idx] = make_float4(C1, C3, Bc, fr2);
    g_pC[idx] = make_float2(C2, C4);
}

// ============ kernel 1: MLP, register-tiled outer-product GEMM ============
// One CTA per time index t; positions b=0..127 of that t-plane.
__global__ __launch_bounds__(256, 1)
void mlp_kernel(const float* __restrict__ in,
                const float* __restrict__ w1, const float* __restrict__ b1,
                const float* __restrict__ w2, const float* __restrict__ b2,
                const float* __restrict__ w3, const float* __restrict__ b3)
{
    extern __shared__ float sm[];
    const int tid = threadIdx.x;
    const int t   = blockIdx.x;

    // ---- stage inputs: row b = tid>>1, half = tid&1 ----
    {
        int b = tid >> 1, half = tid & 1;
        const float* base = in + ((size_t)b * TT + t) * 20;
        if (half == 0){
            float4 q0 = *(const float4*)(base + 0);
            float4 q1 = *(const float4*)(base + 4);
            sm[PT_OFF + 0*128 + b] = q0.x;   // pet
            sm[PT_OFF + 1*128 + b] = q0.y;   // tmean
            sm[PT_OFF + 2*128 + b] = q0.z;   // prcp
            sm[ATT_OFF + 0*128 + b] = q1.y;  // v5
            sm[ATT_OFF + 1*128 + b] = q1.z;  // v6
            sm[ATT_OFF + 2*128 + b] = q1.w;  // v7
        } else {
            float4 q2 = *(const float4*)(base + 8);
            float4 q3 = *(const float4*)(base + 12);
            float4 q4 = *(const float4*)(base + 16);
            sm[ATT_OFF + 3*128 + b] = q2.x;  sm[ATT_OFF + 4*128 + b] = q2.y;
            sm[ATT_OFF + 5*128 + b] = q2.z;  sm[ATT_OFF + 6*128 + b] = q2.w;
            sm[ATT_OFF + 7*128 + b] = q3.x;  sm[ATT_OFF + 8*128 + b] = q3.y;
            sm[ATT_OFF + 9*128 + b] = q3.z;  sm[ATT_OFF +10*128 + b] = q3.w;
            sm[ATT_OFF +11*128 + b] = q4.x;  sm[ATT_OFF +12*128 + b] = q4.y;
            sm[ATT_OFF +13*128 + b] = q4.z;  sm[ATT_OFF +14*128 + b] = q4.w;
        }
    }
    // ---- stage weights ----
    for (int i = tid; i < 15*256; i += 256) sm[W1_OFF + i] = w1[i];
    sm[B1_OFF + tid] = b1[tid];
    for (int i = tid; i < 256*64; i += 256) sm[W2_OFF + i] = w2[i];
    if (tid < 64) sm[B2_OFF + tid] = b2[tid];
    for (int i = tid; i < 384; i += 256){ int m = i >> 6, j = i & 63; sm[W3_OFF + i] = w3[j*6 + m]; }
    if (tid < 8) sm[B3_OFF + tid] = (tid < 6) ? b3[tid] : 0.f;
    __syncthreads();

    const int bg = tid & 15;     // position group: pairs {bg*2, bg*2+1, 32+bg*2, 32+bg*2+1}
    const int ig = tid >> 4;     // output group

    // ---- stage A: layer 1 (15 -> 256) + tanh -> h_s[i][b] ----
    #pragma unroll 1
    for (int pass = 0; pass < 4; pass++){
        const int i0 = pass*64 + ig*4;
        ull acc[4][4];
        #pragma unroll
        for (int ii = 0; ii < 4; ii++){
            float bb = sm[B1_OFF + i0 + ii];
            ull bv = pk(bb, bb);
            acc[0][ii] = bv; acc[1][ii] = bv; acc[2][ii] = bv; acc[3][ii] = bv;
        }
        #pragma unroll
        for (int k = 0; k < 15; k++){
            const ull* arL = (const ull*)(sm + ATT_OFF + k*128 + bg*4);
            const ull* arH = (const ull*)(sm + ATT_OFF + k*128 + 64 + bg*4);
            ull a0 = arL[0], a1 = arL[1], a2 = arH[0], a3 = arH[1];
            float4 wq = *(const float4*)(sm + W1_OFF + k*256 + i0);
            ull w0 = pk(wq.x, wq.x), w1v = pk(wq.y, wq.y), w2v = pk(wq.z, wq.z), w3v = pk(wq.w, wq.w);
            acc[0][0]=ffma2(a0,w0,acc[0][0]); acc[0][1]=ffma2(a0,w1v,acc[0][1]); acc[0][2]=ffma2(a0,w2v,acc[0][2]); acc[0][3]=ffma2(a0,w3v,acc[0][3]);
            acc[1][0]=ffma2(a1,w0,acc[1][0]); acc[1][1]=ffma2(a1,w1v,acc[1][1]); acc[1][2]=ffma2(a1,w2v,acc[1][2]); acc[1][3]=ffma2(a1,w3v,acc[1][3]);
            acc[2][0]=ffma2(a2,w0,acc[2][0]); acc[2][1]=ffma2(a2,w1v,acc[2][1]); acc[2][2]=ffma2(a2,w2v,acc[2][2]); acc[2][3]=ffma2(a2,w3v,acc[2][3]);
            acc[3][0]=ffma2(a3,w0,acc[3][0]); acc[3][1]=ffma2(a3,w1v,acc[3][1]); acc[3][2]=ffma2(a3,w2v,acc[3][2]); acc[3][3]=ffma2(a3,w3v,acc[3][3]);
        }
        #pragma unroll
        for (int ii = 0; ii < 4; ii++){
            ulonglong2 vL, vH;
            vL.x = tanh2(acc[0][ii]); vL.y = tanh2(acc[1][ii]);
            vH.x = tanh2(acc[2][ii]); vH.y = tanh2(acc[3][ii]);
            *(ulonglong2*)(sm + H_OFF + (i0+ii)*128 + bg*4)      = vL;
            *(ulonglong2*)(sm + H_OFF + (i0+ii)*128 + 64 + bg*4) = vH;
        }
    }
    __syncthreads();

    // ---- stage B: layer 2 (256 -> 64) register-tiled GEMM ----
    ull acc[4][4];
    const int j0 = ig*4;
    #pragma unroll
    for (int jj = 0; jj < 4; jj++){
        float bb = sm[B2_OFF + j0 + jj];
        ull bv = pk(bb, bb);
        acc[0][jj] = bv; acc[1][jj] = bv; acc[2][jj] = bv; acc[3][jj] = bv;
    }
    #pragma unroll 4
    for (int i = 0; i < 256; i++){
        const ull* hrL = (const ull*)(sm + H_OFF + i*128 + bg*4);
        const ull* hrH = (const ull*)(sm + H_OFF + i*128 + 64 + bg*4);
        ull h0 = hrL[0], h1v = hrL[1], h2v = hrH[0], h3v = hrH[1];
        float4 wq = *(const float4*)(sm + W2_OFF + i*64 + j0);
        ull w0 = pk(wq.x, wq.x), w1v = pk(wq.y, wq.y), w2v = pk(wq.z, wq.z), w3v = pk(wq.w, wq.w);
        acc[0][0]=ffma2(h0,w0,acc[0][0]); acc[0][1]=ffma2(h0,w1v,acc[0][1]); acc[0][2]=ffma2(h0,w2v,acc[0][2]); acc[0][3]=ffma2(h0,w3v,acc[0][3]);
        acc[1][0]=ffma2(h1v,w0,acc[1][0]); acc[1][1]=ffma2(h1v,w1v,acc[1][1]); acc[1][2]=ffma2(h1v,w2v,acc[1][2]); acc[1][3]=ffma2(h1v,w3v,acc[1][3]);
        acc[2][0]=ffma2(h2v,w0,acc[2][0]); acc[2][1]=ffma2(h2v,w1v,acc[2][1]); acc[2][2]=ffma2(h2v,w2v,acc[2][2]); acc[2][3]=ffma2(h2v,w3v,acc[2][3]);
        acc[3][0]=ffma2(h3v,w0,acc[3][0]); acc[3][1]=ffma2(h3v,w1v,acc[3][1]); acc[3][2]=ffma2(h3v,w2v,acc[3][2]); acc[3][3]=ffma2(h3v,w3v,acc[3][3]);
    }
    #pragma unroll
    for (int pa = 0; pa < 4; pa++)
        #pragma unroll
        for (int jj = 0; jj < 4; jj++) acc[pa][jj] = tanh2(acc[pa][jj]);

    __syncthreads();   // all h reads done; safe to overwrite h region with g
    #pragma unroll
    for (int jj = 0; jj < 4; jj++){
        ulonglong2 vL, vH;
        vL.x = acc[0][jj]; vL.y = acc[1][jj];
        vH.x = acc[2][jj]; vH.y = acc[3][jj];
        *(ulonglong2*)(sm + H_OFF + (j0+jj)*128 + bg*4)      = vL;
        *(ulonglong2*)(sm + H_OFF + (j0+jj)*128 + 64 + bg*4) = vH;
    }
    __syncthreads();

    // ---- stage C: layer 3 (64 -> 6) + sigmoid + emit ----
    if (tid < 128){
        const int b = tid;
        float gj[64];
        #pragma unroll
        for (int j = 0; j < 64; j++) gj[j] = sm[H_OFF + j*128 + b];
        float pr[6];
        #pragma unroll
        for (int m = 0; m < 6; m++){
            float s = sm[B3_OFF + m];
            #pragma unroll
            for (int j = 0; j < 64; j++) s = fmaf(gj[j], sm[W3_OFF + m*64 + j], s);
            pr[m] = sigm(s);
        }
        emit_consts(t*128 + b, sm[PT_OFF + b], sm[PT_OFF + 128 + b], sm[PT_OFF + 256 + b], pr);
    }
}

// ============ kernel 2: serial scan, 128 chains, 16-deep register prefetch ============
__global__ __launch_bounds__(32, 1)
void scan_kernel()
{
    const int b = blockIdx.x * 32 + threadIdx.x;
    const float4* pA = g_pA + b;
    const float4* pB = g_pB + b;
    const float2* pC = g_pC + b;

    float4 bA[16], bC[16]; float bL[16];
    #pragma unroll
    for (int k = 0; k < 16; k++){
        bA[k] = pA[k*BB]; bC[k] = pB[k*BB]; bL[k] = pC[k*BB].x;
    }

    float s0 = 0.f, s1 = 0.f;
    #pragma unroll 1
    for (int t = 0; t < TT; t += 16){
        #pragma unroll
        for (int u = 0; u < 16; u++){
            float4 a = bA[u]; float4 c = bC[u]; float lq = bL[u];
            int tn = t + u + 16;
            bA[u] = pA[tn*BB]; bC[u] = pB[tn*BB]; bL[u] = pC[tn*BB].x;

            // snow bucket
            float hs0  = rcpf(1.f + ex2f(K10 * s0));
            float melt = a.z * hs0 * fminf(s0, a.w);
            s0 += clipf(a.x - melt);

            // soil bucket (fully folded constants, d eliminated)
            float above = rcpf(1.f + ex2f(fmaf(K10, s1, c.x)));   // sigma(10(s1-smax))
            float h1    = rcpf(1.f + ex2f(K10 * s1));
            float E     = ex2f(fmaf(c.w, s1, lq));                // qmax*exp(-f(smax-s1))
            float v     = fmaf(c.z, s1, E);                       // pet/smax*s1 + qmax*exp(..)
            float w     = fmaf(1.f - above, v, above * (c.y + s1)); // c.y = pet+qmax-smax
            s1 += clipf(a.y + melt - h1 * w);

            g_s1s[(t + u) * BB + b] = s1;
        }
    }
}

// ============ kernel 3: q = qsub+qsurf from stored s1 ============
__global__ __launch_bounds__(256)
void qout_kernel(float* __restrict__ out)
{
    int idx = blockIdx.x * 256 + threadIdx.x;
    if (idx >= NP) return;
    float  s1 = g_s1s[idx];
    float4 c  = g_pB[idx];   // C1, C3, Bc, fr2
    float2 e  = g_pC[idx];   // C2, C4
    float above = rcpf(1.f + ex2f(fmaf(K10, s1, c.x)));
    float h1    = rcpf(1.f + ex2f(K10 * s1));
    float E     = ex2f(fmaf(c.w, s1, e.x));
    float q     = h1 * (above * (e.y + s1) + (1.f - above) * E);
    int t = idx >> 7, b = idx & 127;
    out[(size_t)b * TT + t] = q;
}

// ---------------- launch ----------------
extern "C" void kernel_launch(void* const* d_in, const int* in_sizes, int n_in,
                              void* d_out, int out_size)
{
    const float* in = (const float*)d_in[0];
    const float* w1 = (const float*)d_in[1];
    const float* b1 = (const float*)d_in[2];
    const float* w2 = (const float*)d_in[3];
    const float* b2 = (const float*)d_in[4];
    const float* w3 = (const float*)d_in[5];
    const float* b3 = (const float*)d_in[6];
    float* out = (float*)d_out;

    cudaFuncSetAttribute(mlp_kernel, cudaFuncAttributeMaxDynamicSharedMemorySize, SMEM_BYTES);
    mlp_kernel<<<TT, 256, SMEM_BYTES>>>(in, w1, b1, w2, b2, w3, b3);
    scan_kernel<<<4, 32>>>();
    qout_kernel<<<(NP + 255)/256, 256>>>(out);
}

// round 3
// speedup vs baseline: 1.5298x; 1.1607x over previous
#include <cuda_runtime.h>
#include <cstdint>

#define BB 128
#define TT 4096
#define NP (BB*TT)
#define CLIPV 100000.0f
#define K10  (-14.4269504088896340f)   // -10*log2(e)
#define KT2  (-2.8853900817779268f)    // -2*log2(e)  (tanh)
#define KS1  (-1.4426950408889634f)    // -1*log2(e)  (sigmoid)
#define LFR  (0.14426950408889634f)    // 0.1*log2(e)

// ---------------- scratch (device-global, no allocation) ----------------
__device__ float4 g_pA[(TT+16)*BB];   // psnow, prain, g(melt gate), m2(melt cap)
__device__ float4 g_pB[(TT+16)*BB];   // C1t=-5*smax, C3=pet+qmax-smax, Bc=pet/smax, fr2
__device__ float2 g_pC[(TT+16)*BB];   // C2=log2(qmax)-fr2*smax, C4=qmax-smax
__device__ float  g_s1s[TT*BB];       // s1 trajectory

typedef unsigned long long ull;

__device__ __forceinline__ float ex2f(float x){ float y; asm("ex2.approx.f32 %0, %1;" : "=f"(y) : "f"(x)); return y; }
__device__ __forceinline__ float rcpf(float x){ float y; asm("rcp.approx.f32 %0, %1;" : "=f"(y) : "f"(x)); return y; }
__device__ __forceinline__ float lg2f(float x){ float y; asm("lg2.approx.f32 %0, %1;" : "=f"(y) : "f"(x)); return y; }
__device__ __forceinline__ float th_hw(float x){ float y; asm("tanh.approx.f32 %0, %1;" : "=f"(y) : "f"(x)); return y; }
// heaviside(x) == (tanh(5x)+1)/2 == sigma(10x)
__device__ __forceinline__ float hv10(float x){ return rcpf(1.f + ex2f(K10 * x)); }
__device__ __forceinline__ float tanh_fast(float x){ return fmaf(2.f, rcpf(1.f + ex2f(KT2 * x)), -1.f); }
__device__ __forceinline__ float sigm(float x){ return rcpf(1.f + ex2f(KS1 * x)); }
__device__ __forceinline__ float clipf(float x){ return fminf(fmaxf(x, -CLIPV), CLIPV); }

__device__ __forceinline__ ull pk(float lo, float hi){ ull r; asm("mov.b64 %0, {%1, %2};" : "=l"(r) : "f"(lo), "f"(hi)); return r; }
__device__ __forceinline__ void upk(ull v, float& lo, float& hi){ asm("mov.b64 {%0, %1}, %2;" : "=f"(lo), "=f"(hi) : "l"(v)); }
__device__ __forceinline__ ull ffma2(ull a, ull b, ull c){ ull d; asm("fma.rn.f32x2 %0, %1, %2, %3;" : "=l"(d) : "l"(a), "l"(b), "l"(c)); return d; }
__device__ __forceinline__ ull fadd2(ull a, ull b){ ull d; asm("add.rn.f32x2 %0, %1, %2;" : "=l"(d) : "l"(a), "l"(b)); return d; }
__device__ __forceinline__ ull tanh2(ull v){ float lo, hi; upk(v, lo, hi); return pk(tanh_fast(lo), tanh_fast(hi)); }
__device__ __forceinline__ ull shfl16(ull v){
    unsigned lo = (unsigned)v, hi = (unsigned)(v >> 32);
    lo = __shfl_down_sync(0xffffffffu, lo, 16);
    hi = __shfl_down_sync(0xffffffffu, hi, 16);
    return ((ull)hi << 32) | lo;
}

// ---------------- SMEM layout (floats), 64-position tile ----------------
#define ATT_OFF 0                        // attrs[15][64]
#define PT_OFF  (ATT_OFF + 15*64)        // pt[3][64]
#define W1_OFF  (PT_OFF + 3*64)          // w1[15][256]   (reused as g[64][64] later)
#define B1_OFF  (W1_OFF + 15*256)        // 256
#define B2_OFF  (B1_OFF + 256)           // 64
#define W3_OFF  (B2_OFF + 64)            // w3t[6][64]
#define B3_OFF  (W3_OFF + 6*64)          // 8
#define H_OFF   (B3_OFF + 8)             // h[256][64]
#define G_OFF   W1_OFF                   // g[64][64] overlays w1 (dead after stage A)
#define SMEM_FLOATS (H_OFF + 256*64)
#define SMEM_BYTES (SMEM_FLOATS * 4)     // 88352 B -> 2 CTAs/SM

__device__ __forceinline__ void emit_consts(int idx, float pet, float tmean, float prcp, const float p[6]){
    float tmin = p[0], tmax = p[1], ddf = p[2], f = p[3], sm0 = p[4], qm0 = p[5];
    float smax = fmaf(sm0, 1400.f, 100.f);
    float qmax = fmaf(qm0, 40.f, 10.f);
    float tmn   = tmin * (-3.f);
    float psnow = hv10(tmn - tmean) * prcp;
    float prain = prcp - psnow;
    float tmx3  = tmax * 3.f;
    float g     = hv10(tmean - tmx3);
    float m2    = (ddf * 5.f) * (tmean - tmx3);
    float fr2   = f * LFR;
    float C1t   = -5.f * smax;
    float C3    = pet + qmax - smax;
    float Bc    = pet * rcpf(smax);
    float C2    = lg2f(qmax) - fr2 * smax;
    float C4    = qmax - smax;
    g_pA[idx] = make_float4(psnow, prain, g, m2);
    g_pB[idx] = make_float4(C1t, C3, Bc, fr2);
    g_pC[idx] = make_float2(C2, C4);
}

// ============ kernel 1: MLP — 64 positions per CTA, w2 streamed from L2 ============
__global__ __launch_bounds__(256, 2)
void mlp_kernel(const float* __restrict__ in,
                const float* __restrict__ w1, const float* __restrict__ b1,
                const float* __restrict__ w2, const float* __restrict__ b2,
                const float* __restrict__ w3, const float* __restrict__ b3)
{
    extern __shared__ float sm[];
    const int tid = threadIdx.x;
    const int t   = blockIdx.x >> 1;
    const int hb  = blockIdx.x & 1;        // which 64-position half

    // ---- stage inputs ----
    {
        int r = tid >> 2, part = tid & 3;          // r: local row 0..63
        const float* base = in + ((size_t)(hb*64 + r) * TT + t) * 20;
        float4 q = *(const float4*)(base + part*4);
        if (part == 0){
            sm[PT_OFF + 0*64 + r] = q.x;           // pet
            sm[PT_OFF + 1*64 + r] = q.y;           // tmean
            sm[PT_OFF + 2*64 + r] = q.z;           // prcp
            float4 q4 = *(const float4*)(base + 16);
            sm[ATT_OFF + 11*64 + r] = q4.x; sm[ATT_OFF + 12*64 + r] = q4.y;
            sm[ATT_OFF + 13*64 + r] = q4.z; sm[ATT_OFF + 14*64 + r] = q4.w;
        } else if (part == 1){
            sm[ATT_OFF + 0*64 + r] = q.y; sm[ATT_OFF + 1*64 + r] = q.z; sm[ATT_OFF + 2*64 + r] = q.w;
        } else if (part == 2){
            sm[ATT_OFF + 3*64 + r] = q.x; sm[ATT_OFF + 4*64 + r] = q.y;
            sm[ATT_OFF + 5*64 + r] = q.z; sm[ATT_OFF + 6*64 + r] = q.w;
        } else {
            sm[ATT_OFF + 7*64 + r] = q.x; sm[ATT_OFF + 8*64 + r] = q.y;
            sm[ATT_OFF + 9*64 + r] = q.z; sm[ATT_OFF +10*64 + r] = q.w;
        }
    }
    // ---- stage small weights (w2 stays in L2) ----
    for (int i = tid; i < 15*256; i += 256) sm[W1_OFF + i] = w1[i];
    sm[B1_OFF + tid] = b1[tid];
    if (tid < 64) sm[B2_OFF + tid] = b2[tid];
    for (int i = tid; i < 384; i += 256){ int m = i >> 6, j = i & 63; sm[W3_OFF + i] = w3[j*6 + m]; }
    if (tid < 8) sm[B3_OFF + tid] = (tid < 6) ? b3[tid] : 0.f;
    __syncthreads();

    const int bg = tid & 15;        // position group: pairs {bg*2,bg*2+1} and {32+bg*2, 32+bg*2+1}

    // ---- stage A: layer 1 (15 -> 256) + tanh -> h[i][pos] ----
    {
        const int ig = tid >> 4;    // 16 hidden groups of 4
        #pragma unroll 1
        for (int pass = 0; pass < 4; pass++){
            const int i0 = pass*64 + ig*4;
            ull accL[4], accH[4];
            #pragma unroll
            for (int ii = 0; ii < 4; ii++){
                float bb = sm[B1_OFF + i0 + ii];
                accL[ii] = pk(bb, bb); accH[ii] = accL[ii];
            }
            #pragma unroll
            for (int k = 0; k < 15; k++){
                ull aL = *(const ull*)(sm + ATT_OFF + k*64 + bg*2);
                ull aH = *(const ull*)(sm + ATT_OFF + k*64 + 32 + bg*2);
                float4 wq = *(const float4*)(sm + W1_OFF + k*256 + i0);
                ull w0 = pk(wq.x, wq.x), w1v = pk(wq.y, wq.y), w2v = pk(wq.z, wq.z), w3v = pk(wq.w, wq.w);
                accL[0]=ffma2(aL,w0,accL[0]); accL[1]=ffma2(aL,w1v,accL[1]); accL[2]=ffma2(aL,w2v,accL[2]); accL[3]=ffma2(aL,w3v,accL[3]);
                accH[0]=ffma2(aH,w0,accH[0]); accH[1]=ffma2(aH,w1v,accH[1]); accH[2]=ffma2(aH,w2v,accH[2]); accH[3]=ffma2(aH,w3v,accH[3]);
            }
            #pragma unroll
            for (int ii = 0; ii < 4; ii++){
                *(ull*)(sm + H_OFF + (i0+ii)*64 + bg*2)      = tanh2(accL[ii]);
                *(ull*)(sm + H_OFF + (i0+ii)*64 + 32 + bg*2) = tanh2(accH[ii]);
            }
        }
    }
    __syncthreads();

    // ---- stage B: layer 2 (256 -> 64), split-K (kg in-warp), w2 from L2 ----
    {
        const int kg = (tid >> 4) & 1;   // K half: i in [kg*128, kg*128+128)
        const int hg = tid >> 5;         // 8 output groups of 8; j0 = hg*8
        const int j0 = hg * 8;

        ull accL[8], accH[8];
        #pragma unroll
        for (int o = 0; o < 8; o++){
            if (kg == 0){ float bb = sm[B2_OFF + j0 + o]; accL[o] = pk(bb, bb); }
            else accL[o] = 0ULL;
            accH[o] = (kg == 0) ? accL[o] : 0ULL;
        }

        const float4* wp = (const float4*)w2 + hg*2;   // row i -> wp[i*16], wp[i*16+1]
        const int ibase = kg * 128;
        float4 wb[4][2];
        #pragma unroll
        for (int p = 0; p < 4; p++){
            wb[p][0] = __ldg(wp + (size_t)(ibase+p)*16);
            wb[p][1] = __ldg(wp + (size_t)(ibase+p)*16 + 1);
        }

        #pragma unroll 4
        for (int ii = 0; ii < 128; ii++){
            const int slot = ii & 3;
            float4 w0 = wb[slot][0], w1q = wb[slot][1];
            int nn = ii + 4;
            if (nn < 128){
                wb[slot][0] = __ldg(wp + (size_t)(ibase+nn)*16);
                wb[slot][1] = __ldg(wp + (size_t)(ibase+nn)*16 + 1);
            }
            const int i = ibase + ii;
            ull hL = *(const ull*)(sm + H_OFF + i*64 + bg*2);
            ull hH = *(const ull*)(sm + H_OFF + i*64 + 32 + bg*2);
            ull p0 = pk(w0.x,w0.x), p1 = pk(w0.y,w0.y), p2 = pk(w0.z,w0.z), p3 = pk(w0.w,w0.w);
            ull p4 = pk(w1q.x,w1q.x), p5 = pk(w1q.y,w1q.y), p6 = pk(w1q.z,w1q.z), p7 = pk(w1q.w,w1q.w);
            accL[0]=ffma2(hL,p0,accL[0]); accL[1]=ffma2(hL,p1,accL[1]); accL[2]=ffma2(hL,p2,accL[2]); accL[3]=ffma2(hL,p3,accL[3]);
            accL[4]=ffma2(hL,p4,accL[4]); accL[5]=ffma2(hL,p5,accL[5]); accL[6]=ffma2(hL,p6,accL[6]); accL[7]=ffma2(hL,p7,accL[7]);
            accH[0]=ffma2(hH,p0,accH[0]); accH[1]=ffma2(hH,p1,accH[1]); accH[2]=ffma2(hH,p2,accH[2]); accH[3]=ffma2(hH,p3,accH[3]);
            accH[4]=ffma2(hH,p4,accH[4]); accH[5]=ffma2(hH,p5,accH[5]); accH[6]=ffma2(hH,p6,accH[6]); accH[7]=ffma2(hH,p7,accH[7]);
        }

        // in-warp split-K reduction (lanes 16..31 -> lanes 0..15)
        #pragma unroll
        for (int o = 0; o < 8; o++){
            accL[o] = fadd2(accL[o], shfl16(accL[o]));
            accH[o] = fadd2(accH[o], shfl16(accH[o]));
        }

        __syncthreads();   // all h reads done (w1/g overlay is separate; this guards nothing for g, but orders H reuse semantics for safety of later stages)

        if (kg == 0){
            #pragma unroll
            for (int o = 0; o < 8; o++){
                *(ull*)(sm + G_OFF + (j0+o)*64 + bg*2)      = tanh2(accL[o]);
                *(ull*)(sm + G_OFF + (j0+o)*64 + 32 + bg*2) = tanh2(accH[o]);
            }
        }
    }
    __syncthreads();

    // ---- stage C: layer 3 (64 -> 6) + sigmoid + emit ----
    if (tid < 64){
        const int b = tid;
        float pr[6];
        #pragma unroll
        for (int m = 0; m < 6; m++){
            float s = sm[B3_OFF + m];
            #pragma unroll
            for (int j = 0; j < 64; j++)
                s = fmaf(sm[G_OFF + j*64 + b], sm[W3_OFF + m*64 + j], s);
            pr[m] = sigm(s);
        }
        emit_consts(t*128 + hb*64 + b, sm[PT_OFF + b], sm[PT_OFF + 64 + b], sm[PT_OFF + 128 + b], pr);
    }
}

// ============ kernel 2: serial scan, hardware tanh gates, 16-deep prefetch ============
__global__ __launch_bounds__(32, 1)
void scan_kernel()
{
    const int b = blockIdx.x * 32 + threadIdx.x;
    const float4* pA = g_pA + b;
    const float4* pB = g_pB + b;
    const float2* pC = g_pC + b;

    float4 bA[16], bC[16]; float bL[16];
    #pragma unroll
    for (int k = 0; k < 16; k++){
        bA[k] = pA[k*BB]; bC[k] = pB[k*BB]; bL[k] = pC[k*BB].x;
    }

    float s0 = 0.f, s1 = 0.f;
    #pragma unroll 1
    for (int t = 0; t < TT; t += 16){
        #pragma unroll
        for (int u = 0; u < 16; u++){
            float4 a = bA[u]; float4 c = bC[u]; float lq = bL[u];
            int tn = t + u + 16;
            bA[u] = pA[tn*BB]; bC[u] = pB[tn*BB]; bL[u] = pC[tn*BB].x;

            // snow bucket: heaviside(s0) = 0.5*tanh(5 s0)+0.5
            float hs0  = fmaf(0.5f, th_hw(5.f * s0), 0.5f);
            float melt = a.z * hs0 * fminf(s0, a.w);
            s0 += clipf(a.x - melt);

            // soil bucket
            float tA    = th_hw(fmaf(5.f, s1, c.x));      // tanh(5(s1-smax)), c.x = -5*smax
            float above = fmaf( 0.5f, tA, 0.5f);
            float below = fmaf(-0.5f, tA, 0.5f);
            float h1    = fmaf(0.5f, th_hw(5.f * s1), 0.5f);
            float E     = ex2f(fmaf(c.w, s1, lq));        // qmax * exp(-f(smax-s1))
            float v     = fmaf(c.z, s1, E);               // pet/smax*s1 + qmax*exp(..)
            float w     = fmaf(below, v, above * (c.y + s1)); // c.y = pet+qmax-smax
            s1 += clipf(a.y + melt - h1 * w);

            g_s1s[(t + u) * BB + b] = s1;
        }
    }
}

// ============ kernel 3: q = qsub+qsurf from stored s1 ============
__global__ __launch_bounds__(256)
void qout_kernel(float* __restrict__ out)
{
    int idx = blockIdx.x * 256 + threadIdx.x;
    if (idx >= NP) return;
    float  s1 = g_s1s[idx];
    float4 c  = g_pB[idx];   // C1t, C3, Bc, fr2
    float2 e  = g_pC[idx];   // C2, C4
    float tA    = th_hw(fmaf(5.f, s1, c.x));
    float above = fmaf( 0.5f, tA, 0.5f);
    float below = fmaf(-0.5f, tA, 0.5f);
    float h1    = fmaf(0.5f, th_hw(5.f * s1), 0.5f);
    float E     = ex2f(fmaf(c.w, s1, e.x));
    float q     = h1 * (above * (e.y + s1) + below * E);
    int t = idx >> 7, b = idx & 127;
    out[(size_t)b * TT + t] = q;
}

// ---------------- launch ----------------
extern "C" void kernel_launch(void* const* d_in, const int* in_sizes, int n_in,
                              void* d_out, int out_size)
{
    const float* in = (const float*)d_in[0];
    const float* w1 = (const float*)d_in[1];
    const float* b1 = (const float*)d_in[2];
    const float* w2 = (const float*)d_in[3];
    const float* b2 = (const float*)d_in[4];
    const float* w3 = (const float*)d_in[5];
    const float* b3 = (const float*)d_in[6];
    float* out = (float*)d_out;

    cudaFuncSetAttribute(mlp_kernel, cudaFuncAttributeMaxDynamicSharedMemorySize, SMEM_BYTES);
    mlp_kernel<<<TT*2, 256, SMEM_BYTES>>>(in, w1, b1, w2, b2, w3, b3);
    scan_kernel<<<4, 32>>>();
    qout_kernel<<<(NP + 255)/256, 256>>>(out);
}